// round 3
// baseline (speedup 1.0000x reference)
#include <cuda_runtime.h>
#include <cstdint>
#include <math.h>

#define BATCH 8192
#define TDIM 64
#define FDIM 64
#define CWIN 20
#define WWIN 30
#define EF   64
#define BEGIN 15
#define ROWS 49                 // C + W - 1
#define OUT_ROW (5*EF)          // 320
#define OUT_STRIDE (WWIN*OUT_ROW) // 9600 floats per batch

// ---------------------------------------------------------------------------
// Kernel 1: per-batch window stats (mean, std(ddof=1), max, min)
// One CTA per batch. HBM-bound; measured ~4.7 TB/s effective. Unchanged.
// ---------------------------------------------------------------------------
__global__ __launch_bounds__(256) void stats_kernel(const float* __restrict__ x,
                                                    float* __restrict__ out) {
    __shared__ float s[ROWS * FDIM];   // 12544 B
    const int b = blockIdx.x;
    const float* xb = x + (size_t)b * TDIM * FDIM + BEGIN * FDIM;

    const float4* src4 = (const float4*)xb;
    float4* s4 = (float4*)s;
    for (int i = threadIdx.x; i < ROWS * FDIM / 4; i += 256) s4[i] = src4[i];
    __syncthreads();

    float* outb = out + (size_t)b * OUT_STRIDE;
    for (int item = threadIdx.x; item < WWIN * EF; item += 256) {
        const int w = item >> 6;
        const int e = item & 63;
        const float* p = s + w * FDIM + e;   // lane==e -> conflict-free LDS

        float v0 = p[0];
        float sum = v0, mx = v0, mn = v0;
        #pragma unroll
        for (int c = 1; c < CWIN; c++) {
            float v = p[c * FDIM];
            sum += v;
            mx = fmaxf(mx, v);
            mn = fminf(mn, v);
        }
        const float mean = sum * (1.0f / CWIN);
        float var = 0.0f;
        #pragma unroll
        for (int c = 0; c < CWIN; c++) {
            float d = p[c * FDIM] - mean;
            var += d * d;
        }
        const float sd = sqrtf(var * (1.0f / (CWIN - 1)));

        float* o = outb + w * OUT_ROW + e;   // coalesced 128B per field
        o[0]      = mean;
        o[EF]     = sd;
        o[3 * EF] = mx;
        o[4 * EF] = mn;
    }
}

// ---------------------------------------------------------------------------
// Kernel 2: exact descending rank (stable ties by index) per (w,e) column.
// One CTA (1024 thr) per column.
//   key u = ord(-v)  (ascending u == descending v)
//   key64 = (u << 13) | b  -> unique, lexicographic (u, idx) order
//   rank[b] = #{key64' < key64}
// 14-bit histogram -> scan -> grouped scatter of key64 -> warp-cooperative
// per-bin counting (broadcast LDS, no divergence, no dependent-load chains).
// ---------------------------------------------------------------------------
#define NBINS 16384
#define KSHIFT 18                  // 32 - 14
#define RT 1024
#define DYN_SMEM (NBINS*4 + BATCH*8)   // 64 KB + 64 KB = 131072 B

__global__ __launch_bounds__(RT, 1) void rank_kernel(const float* __restrict__ x,
                                                     float* __restrict__ out) {
    extern __shared__ unsigned char dyn[];
    unsigned int*       hist = (unsigned int*)dyn;                  // 64 KB
    unsigned long long* S    = (unsigned long long*)(dyn + NBINS*4);// 64 KB
    __shared__ unsigned int warpSums[32];

    const int col = blockIdx.x;         // col = w*64 + e
    const int w = col >> 6;
    const int e = col & 63;
    const int t = threadIdx.x;
    const int lane = t & 31;
    const int wid  = t >> 5;
    const int row = BEGIN + w + (CWIN - 1);   // 34 + w

    for (int i = t; i < NBINS; i += RT) hist[i] = 0;

    // load column; build monotone keys
    unsigned int myu[8];
    #pragma unroll
    for (int k = 0; k < 8; k++) {
        const int b = t + k * RT;
        float v = __ldg(&x[(size_t)b * TDIM * FDIM + row * FDIM + e]);
        unsigned int f = __float_as_uint(-v);
        myu[k] = (f & 0x80000000u) ? ~f : (f | 0x80000000u);
    }
    __syncthreads();

    #pragma unroll
    for (int k = 0; k < 8; k++) atomicAdd(&hist[myu[k] >> KSHIFT], 1u);
    __syncthreads();

    // exclusive scan of 16384 bins: each warp scans a contiguous 512-bin chunk
    const int wbase = wid * 512;
    unsigned int carry = 0;
    #pragma unroll
    for (int r = 0; r < 16; r++) {
        unsigned int v = hist[wbase + r * 32 + lane];
        unsigned int inc = v;
        #pragma unroll
        for (int d = 1; d < 32; d <<= 1) {
            unsigned int n = __shfl_up_sync(0xffffffffu, inc, d);
            if (lane >= d) inc += n;
        }
        hist[wbase + r * 32 + lane] = (inc - v) + carry;
        carry += __shfl_sync(0xffffffffu, inc, 31);
    }
    if (lane == 31) warpSums[wid] = carry;
    __syncthreads();
    if (wid == 0) {
        unsigned int orig = warpSums[lane];
        unsigned int inc = orig;
        #pragma unroll
        for (int d = 1; d < 32; d <<= 1) {
            unsigned int n = __shfl_up_sync(0xffffffffu, inc, d);
            if (lane >= d) inc += n;
        }
        warpSums[lane] = inc - orig;
    }
    __syncthreads();
    {
        const unsigned int add = warpSums[wid];
        if (add) {
            #pragma unroll
            for (int r = 0; r < 16; r++) hist[wbase + r * 32 + lane] += add;
        }
    }
    __syncthreads();

    // grouped scatter of full keys: hist[bin] walks from excl to incl
    #pragma unroll
    for (int k = 0; k < 8; k++) {
        const unsigned int b = (unsigned int)(t + k * RT);
        unsigned int pos = atomicAdd(&hist[myu[k] >> KSHIFT], 1u);
        S[pos] = ((unsigned long long)myu[k] << 13) | b;
    }
    __syncthreads();

    // warp-cooperative bin walk. Post-scatter: hist[bin] = inclusive count.
    float* outc = out + (size_t)w * OUT_ROW + 2 * EF + e;
    const float invB = 1.0f / BATCH;

    for (int base = wid * 32; base < NBINS; base += 32 * 32) {
        const int bin = base + lane;
        unsigned int incv = hist[bin];
        unsigned int prevv = __shfl_up_sync(0xffffffffu, incv, 1);
        if (lane == 0) prevv = base ? hist[base - 1] : 0u;
        const unsigned int c = incv - prevv;

        // singles: rank == exclusive base, resolved lane-parallel, zero compares
        if (c == 1u) {
            unsigned long long key = S[prevv];
            unsigned int b = (unsigned int)key & 8191u;
            outc[(size_t)b * OUT_STRIDE] = (float)prevv * invB;
        }

        unsigned int m2 = __ballot_sync(0xffffffffu, c > 1u);
        while (m2) {
            const int j = __ffs(m2) - 1;
            m2 &= m2 - 1u;
            const unsigned int bs = __shfl_sync(0xffffffffu, prevv, j);
            const unsigned int cc = __shfl_sync(0xffffffffu, c, j);

            if (cc <= 32u) {
                unsigned long long mk = 0ull;
                const bool act = (unsigned)lane < cc;
                if (act) mk = S[bs + lane];
                unsigned int cnt = 0;
                for (unsigned int jj = 0; jj < cc; jj++) {
                    unsigned long long kj = S[bs + jj];   // broadcast LDS
                    cnt += (kj < mk);
                }
                if (act) {
                    unsigned int b = (unsigned int)mk & 8191u;
                    outc[(size_t)b * OUT_STRIDE] = (float)(bs + cnt) * invB;
                }
            } else if (cc <= 128u) {
                unsigned long long mk[4] = {0ull, 0ull, 0ull, 0ull};
                unsigned int cnt[4] = {0u, 0u, 0u, 0u};
                int nm = 0;
                for (unsigned int i = lane; i < cc; i += 32) mk[nm++] = S[bs + i];
                for (unsigned int jj = 0; jj < cc; jj++) {
                    unsigned long long kj = S[bs + jj];   // broadcast LDS
                    #pragma unroll
                    for (int r = 0; r < 4; r++)
                        cnt[r] += (r < nm) && (kj < mk[r]);
                }
                for (int r = 0; r < nm; r++) {
                    unsigned int b = (unsigned int)mk[r] & 8191u;
                    outc[(size_t)b * OUT_STRIDE] = (float)(bs + cnt[r]) * invB;
                }
            } else {
                // rare giant bin: generic path
                for (unsigned int i = lane; i < cc; i += 32) {
                    unsigned long long mk2 = S[bs + i];
                    unsigned int cnt2 = 0;
                    for (unsigned int jj = 0; jj < cc; jj++)
                        cnt2 += (S[bs + jj] < mk2);
                    unsigned int b = (unsigned int)mk2 & 8191u;
                    outc[(size_t)b * OUT_STRIDE] = (float)(bs + cnt2) * invB;
                }
            }
        }
    }
}

// ---------------------------------------------------------------------------
extern "C" void kernel_launch(void* const* d_in, const int* in_sizes, int n_in,
                              void* d_out, int out_size) {
    const float* x = (const float*)d_in[0];
    float* out = (float*)d_out;

    cudaFuncSetAttribute(rank_kernel, cudaFuncAttributeMaxDynamicSharedMemorySize,
                         DYN_SMEM);

    stats_kernel<<<BATCH, 256>>>(x, out);
    rank_kernel<<<WWIN * EF, RT, DYN_SMEM>>>(x, out);
}

// round 4
// speedup vs baseline: 2.8058x; 2.8058x over previous
#include <cuda_runtime.h>
#include <cstdint>
#include <math.h>

#define BATCH 8192
#define TDIM 64
#define FDIM 64
#define CWIN 20
#define WWIN 30
#define EF   64
#define BEGIN 15
#define ROWS 49                 // C + W - 1
#define OUT_ROW (5*EF)          // 320
#define OUT_STRIDE (WWIN*OUT_ROW) // 9600 floats per batch

// ---------------------------------------------------------------------------
// Kernel 1: per-batch window stats (mean, std(ddof=1), max, min). Unchanged
// (HBM-bound, ~75us).
// ---------------------------------------------------------------------------
__global__ __launch_bounds__(256) void stats_kernel(const float* __restrict__ x,
                                                    float* __restrict__ out) {
    __shared__ float s[ROWS * FDIM];
    const int b = blockIdx.x;
    const float* xb = x + (size_t)b * TDIM * FDIM + BEGIN * FDIM;

    const float4* src4 = (const float4*)xb;
    float4* s4 = (float4*)s;
    for (int i = threadIdx.x; i < ROWS * FDIM / 4; i += 256) s4[i] = src4[i];
    __syncthreads();

    float* outb = out + (size_t)b * OUT_STRIDE;
    for (int item = threadIdx.x; item < WWIN * EF; item += 256) {
        const int w = item >> 6;
        const int e = item & 63;
        const float* p = s + w * FDIM + e;

        float v0 = p[0];
        float sum = v0, mx = v0, mn = v0;
        #pragma unroll
        for (int c = 1; c < CWIN; c++) {
            float v = p[c * FDIM];
            sum += v;
            mx = fmaxf(mx, v);
            mn = fminf(mn, v);
        }
        const float mean = sum * (1.0f / CWIN);
        float var = 0.0f;
        #pragma unroll
        for (int c = 0; c < CWIN; c++) {
            float d = p[c * FDIM] - mean;
            var += d * d;
        }
        const float sd = sqrtf(var * (1.0f / (CWIN - 1)));

        float* o = outb + w * OUT_ROW + e;
        o[0]      = mean;
        o[EF]     = sd;
        o[3 * EF] = mx;
        o[4 * EF] = mn;
    }
}

// ---------------------------------------------------------------------------
// Equalized monotone binning LUT.
// prefix p = u >> 20 (12 bits). Entry packs (base << 4) | e, where the prefix
// owns 2^e consecutive bins and the sub-bin index is the next e bits of u.
// Exactly monotone by construction: bases are prefix-ordered, sub-bins come
// from subsequent key bits. erf only shapes bin *sizes* (performance), never
// correctness.
// ---------------------------------------------------------------------------
#define NPFX 4096
#define NBINS_MAX 20608
__device__ unsigned int g_lut[NPFX];

__global__ __launch_bounds__(1024) void lut_init_kernel() {
    __shared__ unsigned int cap[NPFX];    // 2^e per prefix
    __shared__ unsigned int tsum[1024];
    const int t = threadIdx.x;

    #pragma unroll
    for (int k = 0; k < 4; k++) {
        const int p = t * 4 + k;
        // value interval of this prefix: invert the monotone map
        // forward: f = bits(-v); o = (f & sign) ? ~f : (f | sign)
        auto o2v = [](unsigned int o) -> float {
            unsigned int f = (o & 0x80000000u) ? (o & 0x7FFFFFFFu) : ~o;
            return -__uint_as_float(f);
        };
        float v_a = o2v((unsigned int)p << 20);          // larger v (o asc = v desc)
        float v_b = o2v((unsigned int)(p + 1) << 20);
        float phi_a = 0.5f * (1.0f + erff(v_a * 0.70710678f));
        float phi_b = 0.5f * (1.0f + erff(v_b * 0.70710678f));
        float mass = phi_a - phi_b;
        int e = 0;
        if (mass > 0.0f && isfinite(mass)) {
            float le = log2f(mass * 16384.0f);
            e = (int)floorf(le);
            if (e < 0) e = 0;
            if (e > 10) e = 10;
        }
        cap[p] = 1u << e;
    }
    __syncthreads();

    // per-thread sum of its 4 entries, then block scan of thread sums
    unsigned int s0 = cap[t * 4] + cap[t * 4 + 1] + cap[t * 4 + 2] + cap[t * 4 + 3];
    const int lane = t & 31, wid = t >> 5;
    unsigned int inc = s0;
    #pragma unroll
    for (int d = 1; d < 32; d <<= 1) {
        unsigned int n = __shfl_up_sync(0xffffffffu, inc, d);
        if (lane >= d) inc += n;
    }
    __shared__ unsigned int wsum[32];
    if (lane == 31) wsum[wid] = inc;
    __syncthreads();
    if (wid == 0) {
        unsigned int v = wsum[lane];
        unsigned int wi = v;
        #pragma unroll
        for (int d = 1; d < 32; d <<= 1) {
            unsigned int n = __shfl_up_sync(0xffffffffu, wi, d);
            if (lane >= d) wi += n;
        }
        wsum[lane] = wi - v;
    }
    __syncthreads();
    tsum[t] = (inc - s0) + wsum[wid];     // exclusive base for this thread's 4
    __syncthreads();

    unsigned int base = tsum[t];
    #pragma unroll
    for (int k = 0; k < 4; k++) {
        const int p = t * 4 + k;
        unsigned int c = cap[p];
        unsigned int e = 31 - __clz(c);
        g_lut[p] = (base << 4) | e;
        base += c;
    }
}

// ---------------------------------------------------------------------------
// Kernel 2: exact descending rank per (w,e) column, equalized bins.
//   u = ord(-v); key64 = (u<<13)|b; rank[b] = #{key' < key}
//   = excl_bin_base + #{same-bin keys < mine}.  Bins are ~Poisson(0.7).
// ---------------------------------------------------------------------------
#define RT 1024
#define DYN_SMEM (NBINS_MAX*4 + BATCH*8 + NPFX*4)   // 82432+65536+16384 = 164352

__global__ __launch_bounds__(RT, 1) void rank_kernel(const float* __restrict__ x,
                                                     float* __restrict__ out) {
    extern __shared__ unsigned char dyn[];
    unsigned int*       hist = (unsigned int*)dyn;                        // 80.5 KB
    unsigned long long* S    = (unsigned long long*)(dyn + NBINS_MAX*4);  // 64 KB
    unsigned int*       lut  = (unsigned int*)(dyn + NBINS_MAX*4 + BATCH*8); // 16 KB
    __shared__ unsigned int warpSums[32];

    const int col = blockIdx.x;
    const int w = col >> 6;
    const int e = col & 63;
    const int t = threadIdx.x;
    const int lane = t & 31;
    const int wid  = t >> 5;
    const int row = BEGIN + w + (CWIN - 1);

    for (int i = t; i < NBINS_MAX; i += RT) hist[i] = 0;
    for (int i = t; i < NPFX; i += RT) lut[i] = __ldg(&g_lut[i]);

    unsigned int myu[8];
    #pragma unroll
    for (int k = 0; k < 8; k++) {
        const int b = t + k * RT;
        float v = __ldg(&x[(size_t)b * TDIM * FDIM + row * FDIM + e]);
        unsigned int f = __float_as_uint(-v);
        myu[k] = (f & 0x80000000u) ? ~f : (f | 0x80000000u);
    }
    __syncthreads();

    unsigned int mybin[8];
    #pragma unroll
    for (int k = 0; k < 8; k++) {
        const unsigned int u = myu[k];
        const unsigned int ent = lut[u >> 20];
        const unsigned int eb = ent & 15u;
        mybin[k] = (ent >> 4) + ((u >> (20 - eb)) & ((1u << eb) - 1u));
        atomicAdd(&hist[mybin[k]], 1u);
    }
    __syncthreads();

    // exclusive scan of NBINS_MAX bins: 32 warps x 644-bin chunks (ceil)
    const int CHUNK = (NBINS_MAX + 31) / 32;     // 644
    const int wbase = wid * CHUNK;
    unsigned int carry = 0;
    for (int r = 0; r < CHUNK / 32 + 1; r++) {
        const int idx = wbase + r * 32 + lane;
        const bool ok = (r * 32 + lane < CHUNK) && (idx < NBINS_MAX);
        unsigned int v = ok ? hist[idx] : 0u;
        unsigned int inc = v;
        #pragma unroll
        for (int d = 1; d < 32; d <<= 1) {
            unsigned int n = __shfl_up_sync(0xffffffffu, inc, d);
            if (lane >= d) inc += n;
        }
        if (ok) hist[idx] = (inc - v) + carry;
        carry += __shfl_sync(0xffffffffu, inc, 31);
    }
    if (lane == 31) warpSums[wid] = carry;
    __syncthreads();
    if (wid == 0) {
        unsigned int orig = warpSums[lane];
        unsigned int inc = orig;
        #pragma unroll
        for (int d = 1; d < 32; d <<= 1) {
            unsigned int n = __shfl_up_sync(0xffffffffu, inc, d);
            if (lane >= d) inc += n;
        }
        warpSums[lane] = inc - orig;
    }
    __syncthreads();
    {
        const unsigned int add = warpSums[wid];
        if (add) {
            for (int r = 0; r < CHUNK / 32 + 1; r++) {
                const int idx = wbase + r * 32 + lane;
                if ((r * 32 + lane < CHUNK) && (idx < NBINS_MAX)) hist[idx] += add;
            }
        }
    }
    __syncthreads();

    // grouped scatter of full keys; hist[bin] walks excl -> incl
    #pragma unroll
    for (int k = 0; k < 8; k++) {
        const unsigned int b = (unsigned int)(t + k * RT);
        unsigned int pos = atomicAdd(&hist[mybin[k]], 1u);
        S[pos] = ((unsigned long long)myu[k] << 13) | b;
    }
    __syncthreads();

    // walk: bins are tiny (avg ~1.7 when occupied). Per-element independent LDS.
    float* outc = out + (size_t)w * OUT_ROW + 2 * EF + e;
    const float invB = 1.0f / BATCH;
    #pragma unroll
    for (int k = 0; k < 8; k++) {
        const int b = t + k * RT;
        const unsigned long long mykey =
            ((unsigned long long)myu[k] << 13) | (unsigned int)b;
        const unsigned int bin = mybin[k];
        const unsigned int start = bin ? hist[bin - 1] : 0u;
        const unsigned int end = hist[bin];
        unsigned int cnt = 0;
        for (unsigned int p = start; p < end; p++)
            cnt += (S[p] < mykey);
        outc[(size_t)b * OUT_STRIDE] = (float)(start + cnt) * invB;
    }
}

// ---------------------------------------------------------------------------
extern "C" void kernel_launch(void* const* d_in, const int* in_sizes, int n_in,
                              void* d_out, int out_size) {
    const float* x = (const float*)d_in[0];
    float* out = (float*)d_out;

    cudaFuncSetAttribute(rank_kernel, cudaFuncAttributeMaxDynamicSharedMemorySize,
                         DYN_SMEM);

    lut_init_kernel<<<1, 1024>>>();
    stats_kernel<<<BATCH, 256>>>(x, out);
    rank_kernel<<<WWIN * EF, RT, DYN_SMEM>>>(x, out);
}